// round 16
// baseline (speedup 1.0000x reference)
#include <cuda_runtime.h>
#include <cuda_fp16.h>
#include <cstdint>
#include <math.h>

#define T_TOK 32768
#define D_DIM 1024
#define F_DIM 2048
#define NE    16
#define NA    (T_TOK * 2)
#define ROWT  128
#define CT1   32
#define CT2   8
#define KT1   16                       // D/64
#define KT2   32                       // F/64
#define MAXT1 ((NA / ROWT + NE) * CT1)
#define MAXT2 ((NA / ROWT + NE) * CT2)
#define RGRID (T_TOK / 32)             // router grid: 1024 blocks

#define ASZ   18432                    // 128 rows * 144B
#define STG1  (ASZ + 2 * 9216)         // 36864
#define STG2  (ASZ + 17408)            // 35840
#define SMEM1 (3 * STG1)
#define SMEM2 (3 * STG2)

// ---------------- device scratch ----------------
__device__ int    g_counts[NE];
__device__ int    g_done;
__device__ int    g_offsets[NE + 1];
__device__ int    g_cursor[NE];
__device__ int    g_te[NA];
__device__ float  g_tw[NA];
__device__ int    g_idx[NA];
__device__ float  g_wgt[NA];
__device__ int    g_tp1[NE + 1];
__device__ int    g_tp2[NE + 1];
__device__ __half g_xh[(size_t)T_TOK * D_DIM];
__device__ __half g_gwh[(size_t)NE * D_DIM * F_DIM];
__device__ __half g_uwh[(size_t)NE * D_DIM * F_DIM];
__device__ __half g_dwh[(size_t)NE * F_DIM * D_DIM];
__device__ __half g_H[(size_t)(NA + ROWT) * F_DIM];

// ---------------- helpers ----------------
__device__ __forceinline__ uint32_t smem_u32(const void* p) {
    uint32_t a;
    asm("{ .reg .u64 t; cvta.to.shared.u64 t, %1; cvt.u32.u64 %0, t; }" : "=r"(a) : "l"(p));
    return a;
}
__device__ __forceinline__ void cpa16(uint32_t s, const void* g) {
    asm volatile("cp.async.cg.shared.global [%0], [%1], 16;" :: "r"(s), "l"(__cvta_generic_to_global(g)) : "memory");
}
#define CP_COMMIT() asm volatile("cp.async.commit_group;" ::: "memory")
#define CP_WAIT(n)  asm volatile("cp.async.wait_group %0;" :: "n"(n) : "memory")

__device__ __forceinline__ void ldsm4(uint32_t* r, uint32_t a) {
    asm volatile("ldmatrix.sync.aligned.m8n8.x4.shared.b16 {%0,%1,%2,%3}, [%4];"
                 : "=r"(r[0]), "=r"(r[1]), "=r"(r[2]), "=r"(r[3]) : "r"(a));
}
__device__ __forceinline__ void ldsm4t(uint32_t* r, uint32_t a) {
    asm volatile("ldmatrix.sync.aligned.m8n8.x4.trans.shared.b16 {%0,%1,%2,%3}, [%4];"
                 : "=r"(r[0]), "=r"(r[1]), "=r"(r[2]), "=r"(r[3]) : "r"(a));
}
__device__ __forceinline__ void mma16816(float* d, const uint32_t* a, const uint32_t* b) {
    asm volatile("mma.sync.aligned.m16n8k16.row.col.f32.f16.f16.f32 "
                 "{%0,%1,%2,%3},{%4,%5,%6,%7},{%8,%9},{%0,%1,%2,%3};"
                 : "+f"(d[0]), "+f"(d[1]), "+f"(d[2]), "+f"(d[3])
                 : "r"(a[0]), "r"(a[1]), "r"(a[2]), "r"(a[3]), "r"(b[0]), "r"(b[1]));
}
__device__ __forceinline__ void redv2(float* p, float a, float b) {
    asm volatile("red.global.add.v2.f32 [%0], {%1, %2};"
                 :: "l"(__cvta_generic_to_global(p)), "f"(a), "f"(b) : "memory");
}

// ---------------- router (fused x->fp16 conversion + tail-block setup) ----------------
__global__ __launch_bounds__(256) void k_router(const float* __restrict__ x,
                                                const float* __restrict__ rw,
                                                float* __restrict__ logits) {
    int warp = threadIdx.x >> 5, lane = threadIdx.x & 31;
    int tok0 = blockIdx.x * 32 + warp * 4;

    float acc[4][NE];
#pragma unroll
    for (int t = 0; t < 4; t++)
#pragma unroll
        for (int e = 0; e < NE; e++) acc[t][e] = 0.f;

    for (int d0 = 0; d0 < D_DIM; d0 += 128) {
        float4 xv[4];
#pragma unroll
        for (int t = 0; t < 4; t++) {
            xv[t] = *reinterpret_cast<const float4*>(x + (size_t)(tok0 + t) * D_DIM + d0 + lane * 4);
            __half2 h0 = __floats2half2_rn(xv[t].x, xv[t].y);
            __half2 h1 = __floats2half2_rn(xv[t].z, xv[t].w);
            *reinterpret_cast<uint2*>(g_xh + (size_t)(tok0 + t) * D_DIM + d0 + lane * 4) =
                make_uint2(*reinterpret_cast<uint32_t*>(&h0), *reinterpret_cast<uint32_t*>(&h1));
        }
#pragma unroll
        for (int e = 0; e < NE; e++) {
            float4 wv = *reinterpret_cast<const float4*>(rw + e * D_DIM + d0 + lane * 4);
#pragma unroll
            for (int t = 0; t < 4; t++)
                acc[t][e] += xv[t].x * wv.x + xv[t].y * wv.y + xv[t].z * wv.z + xv[t].w * wv.w;
        }
    }

#pragma unroll
    for (int t = 0; t < 4; t++) {
        float la[NE];
#pragma unroll
        for (int e = 0; e < NE; e++) {
            float v = acc[t][e];
#pragma unroll
            for (int off = 16; off > 0; off >>= 1)
                v += __shfl_down_sync(0xffffffffu, v, off);
            la[e] = v;
        }
        if (lane == 0) {
            int tok = tok0 + t;
            float* lo = logits + (size_t)tok * NE;
#pragma unroll
            for (int e = 0; e < NE; e++) lo[e] = la[e];
            float m = la[0];
#pragma unroll
            for (int e = 1; e < NE; e++) m = fmaxf(m, la[e]);
            float p[NE], s = 0.f;
#pragma unroll
            for (int e = 0; e < NE; e++) { p[e] = __expf(la[e] - m); s += p[e]; }
            float inv = 1.f / s;
            int i1 = 0; float v1 = la[0];
#pragma unroll
            for (int e = 1; e < NE; e++) if (la[e] > v1) { v1 = la[e]; i1 = e; }
            int i2 = -1; float v2 = -1e30f;
#pragma unroll
            for (int e = 0; e < NE; e++) if (e != i1 && la[e] > v2) { v2 = la[e]; i2 = e; }
            g_te[2 * tok]     = i1; g_tw[2 * tok]     = p[i1] * inv;
            g_te[2 * tok + 1] = i2; g_tw[2 * tok + 1] = p[i2] * inv;
            atomicAdd(&g_counts[i1], 1);
            atomicAdd(&g_counts[i2], 1);
        }
    }

    // tail-block setup: last block to finish computes offsets / tile prefixes
    __syncthreads();
    if (threadIdx.x == 0) {
        int prev = atomicAdd(&g_done, 1);
        if (prev == RGRID - 1) {
            int off = 0, t1 = 0, t2 = 0;
#pragma unroll
            for (int e = 0; e < NE; e++) {
                g_offsets[e] = off; g_cursor[e] = off;
                int c = atomicAdd(&g_counts[e], 0);   // coherent read
                off += c;
                g_tp1[e] = t1; g_tp2[e] = t2;
                int rt = (c + ROWT - 1) >> 7;
                t1 += rt * CT1; t2 += rt * CT2;
            }
            g_offsets[NE] = off; g_tp1[NE] = t1; g_tp2[NE] = t2;
            __threadfence();
        }
    }
}

// block-aggregated scatter: smem histogram + 16 global atomics per block.
__global__ __launch_bounds__(128) void k_scatter() {
    __shared__ int hist[NE], base[NE];
    int tid = threadIdx.x;
    if (tid < NE) hist[tid] = 0;
    __syncthreads();
    int t = blockIdx.x * 128 + tid;
    int e0 = g_te[2 * t], e1 = g_te[2 * t + 1];
    float w0 = g_tw[2 * t], w1 = g_tw[2 * t + 1];
    int r0 = atomicAdd(&hist[e0], 1);
    int r1 = atomicAdd(&hist[e1], 1);
    __syncthreads();
    if (tid < NE) base[tid] = atomicAdd(&g_cursor[tid], hist[tid]);
    __syncthreads();
    int p0 = base[e0] + r0, p1 = base[e1] + r1;
    g_idx[p0] = t; g_wgt[p0] = w0;
    g_idx[p1] = t; g_wgt[p1] = w1;
}

// ---------------- fp32 -> fp16 weight converts ----------------
__global__ __launch_bounds__(256) void k_cvt_gu(const float4* __restrict__ gw,
                                                const float4* __restrict__ uw) {
    size_t i = (size_t)blockIdx.x * 256 + threadIdx.x;
    const size_t N4 = (size_t)NE * D_DIM * F_DIM / 4;
    const float4* src = (i < N4) ? gw : uw;
    __half* dst = (i < N4) ? g_gwh : g_uwh;
    size_t j = (i < N4) ? i : i - N4;
    float4 v = src[j];
    __half2 h0 = __floats2half2_rn(v.x, v.y);
    __half2 h1 = __floats2half2_rn(v.z, v.w);
    reinterpret_cast<uint2*>(dst)[j] =
        make_uint2(*reinterpret_cast<uint32_t*>(&h0), *reinterpret_cast<uint32_t*>(&h1));
}
__global__ __launch_bounds__(256) void k_cvt_d_zero(const float4* __restrict__ dw,
                                                    float4* __restrict__ out4) {
    size_t i = (size_t)blockIdx.x * 256 + threadIdx.x;
    float4 v = dw[i];
    __half2 h0 = __floats2half2_rn(v.x, v.y);
    __half2 h1 = __floats2half2_rn(v.z, v.w);
    reinterpret_cast<uint2*>(g_dwh)[i] =
        make_uint2(*reinterpret_cast<uint32_t*>(&h0), *reinterpret_cast<uint32_t*>(&h1));
    out4[i] = make_float4(0.f, 0.f, 0.f, 0.f);
}

// ---------------- GEMM1: H = silu(X Gw) * (X Uw) ----------------
// CTA 128 rows x 64 cols (gate+up), 256 threads, K-tile 64, 3-stage, 2 CTAs/SM.
__global__ __launch_bounds__(256, 2) void k_mma1() {
    extern __shared__ __align__(16) char smraw[];
    uint32_t sb = smem_u32(smraw);
    __shared__ int info[3];

    int tid = threadIdx.x, w = tid >> 5, l = tid & 31;
    if (tid == 0) {
        int b = blockIdx.x, e = -1;
        if (b < g_tp1[NE]) {
#pragma unroll
            for (int i = 0; i < NE; i++) if (b < g_tp1[i + 1]) { e = i; break; }
        }
        info[0] = e;
        if (e >= 0) { int t = b - g_tp1[e]; info[1] = (t >> 5) << 7; info[2] = (t & 31) << 6; }
    }
    __syncthreads();
    int e = info[0];
    if (e < 0) return;
    int row0 = info[1], col0 = info[2];
    int off = g_offsets[e], n = g_offsets[e + 1] - off;

    const __half* srcA[4]; uint32_t dstA[4];
#pragma unroll
    for (int i = 0; i < 4; i++) {
        int id = tid + i * 256, ar = id >> 3, ch = id & 7;
        int r = row0 + ar; if (r > n - 1) r = n - 1;
        srcA[i] = g_xh + (size_t)g_idx[off + r] * D_DIM + ch * 8;
        dstA[i] = sb + ar * 144 + ch * 16;
    }
    const __half* srcG[2]; const __half* srcU[2]; uint32_t dstB[2];
#pragma unroll
    for (int i = 0; i < 2; i++) {
        int id = tid + i * 256, br = id >> 3, bc = id & 7;
        srcG[i] = g_gwh + ((size_t)e * D_DIM + br) * F_DIM + col0 + bc * 8;
        srcU[i] = g_uwh + ((size_t)e * D_DIM + br) * F_DIM + col0 + bc * 8;
        dstB[i] = sb + ASZ + br * 144 + bc * 16;
    }

    auto load = [&](int kt) {
        uint32_t s = (uint32_t)(kt % 3) * STG1;
        size_t kG = (size_t)kt * 64 * F_DIM;
#pragma unroll
        for (int i = 0; i < 4; i++) cpa16(dstA[i] + s, srcA[i] + kt * 64);
#pragma unroll
        for (int i = 0; i < 2; i++) cpa16(dstB[i] + s, srcG[i] + kG);
#pragma unroll
        for (int i = 0; i < 2; i++) cpa16(dstB[i] + s + 9216, srcU[i] + kG);
        CP_COMMIT();
    };
    load(0); load(1);

    float cg[4][2][4], cu[4][2][4];
#pragma unroll
    for (int mi = 0; mi < 4; mi++)
#pragma unroll
        for (int ni = 0; ni < 2; ni++)
#pragma unroll
            for (int j = 0; j < 4; j++) { cg[mi][ni][j] = 0.f; cu[mi][ni][j] = 0.f; }

    int wm = w >> 2, wn = w & 3;
    int lr = l & 15, lc = l >> 4;
    uint32_t aOff = (uint32_t)((wm * 64 + lr) * 144 + lc * 16);
    uint32_t gOff = (uint32_t)(ASZ + lr * 144 + (wn * 16 + lc * 8) * 2);
    uint32_t uOff = gOff + 9216;

    for (int kt = 0; kt < KT1; kt++) {
        if (kt < KT1 - 1) CP_WAIT(1); else CP_WAIT(0);
        __syncthreads();
        if (kt + 2 < KT1) load(kt + 2);
        uint32_t s = sb + (uint32_t)(kt % 3) * STG1;
#pragma unroll
        for (int ks = 0; ks < 4; ks++) {
            uint32_t a[4][4], bg[4], bu[4];
#pragma unroll
            for (int mi = 0; mi < 4; mi++)
                ldsm4(a[mi], s + aOff + mi * 2304 + ks * 32);
            ldsm4t(bg, s + gOff + ks * 2304);
            ldsm4t(bu, s + uOff + ks * 2304);
#pragma unroll
            for (int mi = 0; mi < 4; mi++)
#pragma unroll
                for (int ni = 0; ni < 2; ni++) {
                    mma16816(cg[mi][ni], a[mi], &bg[2 * ni]);
                    mma16816(cu[mi][ni], a[mi], &bu[2 * ni]);
                }
        }
    }

    // epilogue: silu(g)*u -> smem tile (144B stride) -> coalesced 16B stores
    __syncthreads();
#pragma unroll
    for (int mi = 0; mi < 4; mi++) {
        int rl = wm * 64 + mi * 16 + (l >> 2);
        int rh = rl + 8;
#pragma unroll
        for (int ni = 0; ni < 2; ni++) {
            int cb = (wn * 16 + ni * 8 + 2 * (l & 3)) * 2;
            float g0 = cg[mi][ni][0], g1 = cg[mi][ni][1], g2 = cg[mi][ni][2], g3 = cg[mi][ni][3];
            float h0 = g0 * __fdividef(1.f, 1.f + __expf(-g0)) * cu[mi][ni][0];
            float h1 = g1 * __fdividef(1.f, 1.f + __expf(-g1)) * cu[mi][ni][1];
            float h2 = g2 * __fdividef(1.f, 1.f + __expf(-g2)) * cu[mi][ni][2];
            float h3 = g3 * __fdividef(1.f, 1.f + __expf(-g3)) * cu[mi][ni][3];
            *reinterpret_cast<__half2*>(smraw + rl * 144 + cb) = __floats2half2_rn(h0, h1);
            *reinterpret_cast<__half2*>(smraw + rh * 144 + cb) = __floats2half2_rn(h2, h3);
        }
    }
    __syncthreads();
#pragma unroll
    for (int i = 0; i < 4; i++) {
        int id = tid + i * 256, r = id >> 3, ch = id & 7;
        if (row0 + r < n)
            *reinterpret_cast<uint4*>(&g_H[(size_t)(off + row0 + r) * F_DIM + col0 + ch * 8]) =
                *reinterpret_cast<const uint4*>(smraw + r * 144 + ch * 16);
    }
}

// ---------------- GEMM2: out += w * (H Dw), deterministic red.global ----------------
// CTA 128 rows x 128 cols, 256 threads, K-tile 64, 3-stage, 2 CTAs/SM.
__global__ __launch_bounds__(256, 2) void k_mma2(float* __restrict__ out) {
    extern __shared__ __align__(16) char smraw[];
    uint32_t sb = smem_u32(smraw);
    __shared__ int info[3];

    int tid = threadIdx.x, w = tid >> 5, l = tid & 31;
    if (tid == 0) {
        int b = blockIdx.x, e = -1;
        if (b < g_tp2[NE]) {
#pragma unroll
            for (int i = 0; i < NE; i++) if (b < g_tp2[i + 1]) { e = i; break; }
        }
        info[0] = e;
        if (e >= 0) { int t = b - g_tp2[e]; info[1] = (t >> 3) << 7; info[2] = (t & 7) << 7; }
    }
    __syncthreads();
    int e = info[0];
    if (e < 0) return;
    int row0 = info[1], col0 = info[2];
    int off = g_offsets[e], n = g_offsets[e + 1] - off;

    const __half* srcA[4]; uint32_t dstA[4];
#pragma unroll
    for (int i = 0; i < 4; i++) {
        int id = tid + i * 256, ar = id >> 3, ch = id & 7;
        int r = row0 + ar; if (r > n - 1) r = n - 1;
        srcA[i] = g_H + (size_t)(off + r) * F_DIM + ch * 8;
        dstA[i] = sb + ar * 144 + ch * 16;
    }
    const __half* srcB[4]; uint32_t dstB[4];
#pragma unroll
    for (int i = 0; i < 4; i++) {
        int id = tid + i * 256, brw = id >> 4, ch = id & 15;
        srcB[i] = g_dwh + ((size_t)e * F_DIM + brw) * D_DIM + col0 + ch * 8;
        dstB[i] = sb + ASZ + brw * 272 + ch * 16;
    }

    auto load = [&](int kt) {
        uint32_t s = (uint32_t)(kt % 3) * STG2;
        size_t kB = (size_t)kt * 64 * D_DIM;
#pragma unroll
        for (int i = 0; i < 4; i++) cpa16(dstA[i] + s, srcA[i] + kt * 64);
#pragma unroll
        for (int i = 0; i < 4; i++) cpa16(dstB[i] + s, srcB[i] + kB);
        CP_COMMIT();
    };
    load(0); load(1);

    float cc[4][4][4];
#pragma unroll
    for (int mi = 0; mi < 4; mi++)
#pragma unroll
        for (int ni = 0; ni < 4; ni++)
#pragma unroll
            for (int j = 0; j < 4; j++) cc[mi][ni][j] = 0.f;

    int wm = w >> 2, wn = w & 3;
    int lr = l & 15, lc = l >> 4;
    uint32_t aOff = (uint32_t)((wm * 64 + lr) * 144 + lc * 16);
    uint32_t bOff = (uint32_t)(ASZ + lr * 272 + (wn * 32 + lc * 8) * 2);

    for (int kt = 0; kt < KT2; kt++) {
        if (kt < KT2 - 1) CP_WAIT(1); else CP_WAIT(0);
        __syncthreads();
        if (kt + 2 < KT2) load(kt + 2);
        uint32_t s = sb + (uint32_t)(kt % 3) * STG2;
#pragma unroll
        for (int ks = 0; ks < 4; ks++) {
            uint32_t a[4][4], bf[2][4];
#pragma unroll
            for (int mi = 0; mi < 4; mi++)
                ldsm4(a[mi], s + aOff + mi * 2304 + ks * 32);
#pragma unroll
            for (int nf = 0; nf < 2; nf++)
                ldsm4t(bf[nf], s + bOff + ks * 4352 + nf * 32);
#pragma unroll
            for (int mi = 0; mi < 4; mi++)
#pragma unroll
                for (int ni = 0; ni < 4; ni++)
                    mma16816(cc[mi][ni], a[mi], &bf[ni >> 1][2 * (ni & 1)]);
        }
    }

    // epilogue: deterministic fp32 reduction straight into out (exactly 2 adds/element).
    int cbase = col0 + wn * 32 + 2 * (l & 3);
#pragma unroll
    for (int mi = 0; mi < 4; mi++) {
        int rl = row0 + wm * 64 + mi * 16 + (l >> 2);
        int rh = rl + 8;
        if (rl < n) {
            float wl = g_wgt[off + rl];
            float* po = out + (size_t)g_idx[off + rl] * D_DIM + cbase;
#pragma unroll
            for (int ni = 0; ni < 4; ni++)
                redv2(po + ni * 8, wl * cc[mi][ni][0], wl * cc[mi][ni][1]);
        }
        if (rh < n) {
            float wh = g_wgt[off + rh];
            float* po = out + (size_t)g_idx[off + rh] * D_DIM + cbase;
#pragma unroll
            for (int ni = 0; ni < 4; ni++)
                redv2(po + ni * 8, wh * cc[mi][ni][2], wh * cc[mi][ni][3]);
        }
    }
}

// ---------------- launch ----------------
extern "C" void kernel_launch(void* const* d_in, const int* in_sizes, int n_in,
                              void* d_out, int out_size) {
    const float* x  = (const float*)d_in[0];
    const float* rw = (const float*)d_in[1];
    const float* gw = (const float*)d_in[2];
    const float* uw = (const float*)d_in[3];
    const float* dw = (const float*)d_in[4];
    float* out    = (float*)d_out;
    float* logits = out + (size_t)T_TOK * D_DIM;

    static cudaStream_t s1 = nullptr;
    static cudaEvent_t evF = nullptr, ev1 = nullptr, ev2 = nullptr;
    static void* counts_ptr = nullptr;
    static void* done_ptr = nullptr;
    static int init_done = 0;
    if (!init_done) {
        cudaFuncSetAttribute(k_mma1, cudaFuncAttributeMaxDynamicSharedMemorySize, SMEM1);
        cudaFuncSetAttribute(k_mma2, cudaFuncAttributeMaxDynamicSharedMemorySize, SMEM2);
        cudaStreamCreateWithFlags(&s1, cudaStreamNonBlocking);
        cudaEventCreateWithFlags(&evF, cudaEventDisableTiming);
        cudaEventCreateWithFlags(&ev1, cudaEventDisableTiming);
        cudaEventCreateWithFlags(&ev2, cudaEventDisableTiming);
        cudaGetSymbolAddress(&counts_ptr, g_counts);
        cudaGetSymbolAddress(&done_ptr, g_done);
        init_done = 1;
    }

    // zero expert counters + completion flag (replaces k_init / k_setup launches)
    cudaMemsetAsync(counts_ptr, 0, NE * sizeof(int), 0);
    cudaMemsetAsync(done_ptr, 0, sizeof(int), 0);

    // single side stream, CHAINED: gu first (gates GEMM1, full spare BW),
    // then dw+zero (only needed by GEMM2, overlaps GEMM1).
    cudaEventRecord(evF, 0);
    cudaStreamWaitEvent(s1, evF, 0);
    k_cvt_gu<<<65536, 256, 0, s1>>>((const float4*)gw, (const float4*)uw);
    cudaEventRecord(ev1, s1);
    k_cvt_d_zero<<<32768, 256, 0, s1>>>((const float4*)dw, (float4*)out);
    cudaEventRecord(ev2, s1);

    k_router<<<RGRID, 256>>>(x, rw, logits);   // tail block performs setup inline
    k_scatter<<<T_TOK / 128, 128>>>();

    cudaStreamWaitEvent(0, ev1, 0);
    k_mma1<<<MAXT1, 256, SMEM1>>>();
    cudaStreamWaitEvent(0, ev2, 0);
    k_mma2<<<MAXT2, 256, SMEM2>>>(out);
}

// round 17
// speedup vs baseline: 1.0018x; 1.0018x over previous
#include <cuda_runtime.h>
#include <cuda_fp16.h>
#include <cstdint>
#include <math.h>

#define T_TOK 32768
#define D_DIM 1024
#define F_DIM 2048
#define NE    16
#define NA    (T_TOK * 2)
#define ROWT  128
#define CT1   32
#define CT2   8
#define KT1   16                       // D/64
#define KT2   32                       // F/64
#define MAXT1 ((NA / ROWT + NE) * CT1)
#define MAXT2 ((NA / ROWT + NE) * CT2)

#define ASZ   18432                    // 128 rows * 144B
#define STG1  (ASZ + 2 * 9216)         // 36864
#define STG2  (ASZ + 17408)            // 35840
#define SMEM1 (3 * STG1)
#define SMEM2 (3 * STG2)

// ---------------- device scratch ----------------
__device__ int    g_counts[NE];
__device__ int    g_offsets[NE + 1];
__device__ int    g_cursor[NE];
__device__ int    g_te[NA];
__device__ float  g_tw[NA];
__device__ int    g_idx[NA];
__device__ float  g_wgt[NA];
__device__ int    g_tp1[NE + 1];
__device__ int    g_tp2[NE + 1];
__device__ __half g_xh[(size_t)T_TOK * D_DIM];
__device__ __half g_gwh[(size_t)NE * D_DIM * F_DIM];
__device__ __half g_uwh[(size_t)NE * D_DIM * F_DIM];
__device__ __half g_dwh[(size_t)NE * F_DIM * D_DIM];
__device__ __half g_H[(size_t)(NA + ROWT) * F_DIM];

// ---------------- helpers ----------------
__device__ __forceinline__ uint32_t smem_u32(const void* p) {
    uint32_t a;
    asm("{ .reg .u64 t; cvta.to.shared.u64 t, %1; cvt.u32.u64 %0, t; }" : "=r"(a) : "l"(p));
    return a;
}
__device__ __forceinline__ void cpa16(uint32_t s, const void* g) {
    asm volatile("cp.async.cg.shared.global [%0], [%1], 16;" :: "r"(s), "l"(__cvta_generic_to_global(g)) : "memory");
}
#define CP_COMMIT() asm volatile("cp.async.commit_group;" ::: "memory")
#define CP_WAIT(n)  asm volatile("cp.async.wait_group %0;" :: "n"(n) : "memory")

__device__ __forceinline__ void ldsm4(uint32_t* r, uint32_t a) {
    asm volatile("ldmatrix.sync.aligned.m8n8.x4.shared.b16 {%0,%1,%2,%3}, [%4];"
                 : "=r"(r[0]), "=r"(r[1]), "=r"(r[2]), "=r"(r[3]) : "r"(a));
}
__device__ __forceinline__ void ldsm4t(uint32_t* r, uint32_t a) {
    asm volatile("ldmatrix.sync.aligned.m8n8.x4.trans.shared.b16 {%0,%1,%2,%3}, [%4];"
                 : "=r"(r[0]), "=r"(r[1]), "=r"(r[2]), "=r"(r[3]) : "r"(a));
}
__device__ __forceinline__ void mma16816(float* d, const uint32_t* a, const uint32_t* b) {
    asm volatile("mma.sync.aligned.m16n8k16.row.col.f32.f16.f16.f32 "
                 "{%0,%1,%2,%3},{%4,%5,%6,%7},{%8,%9},{%0,%1,%2,%3};"
                 : "+f"(d[0]), "+f"(d[1]), "+f"(d[2]), "+f"(d[3])
                 : "r"(a[0]), "r"(a[1]), "r"(a[2]), "r"(a[3]), "r"(b[0]), "r"(b[1]));
}
__device__ __forceinline__ void redv2(float* p, float a, float b) {
    asm volatile("red.global.add.v2.f32 [%0], {%1, %2};"
                 :: "l"(__cvta_generic_to_global(p)), "f"(a), "f"(b) : "memory");
}

// ---------------- router (fused x->fp16 conversion: x read once) ----------------
__global__ __launch_bounds__(256) void k_router(const float* __restrict__ x,
                                                const float* __restrict__ rw,
                                                float* __restrict__ logits) {
    int warp = threadIdx.x >> 5, lane = threadIdx.x & 31;
    int tok0 = blockIdx.x * 32 + warp * 4;

    float acc[4][NE];
#pragma unroll
    for (int t = 0; t < 4; t++)
#pragma unroll
        for (int e = 0; e < NE; e++) acc[t][e] = 0.f;

    for (int d0 = 0; d0 < D_DIM; d0 += 128) {
        float4 xv[4];
#pragma unroll
        for (int t = 0; t < 4; t++) {
            xv[t] = *reinterpret_cast<const float4*>(x + (size_t)(tok0 + t) * D_DIM + d0 + lane * 4);
            __half2 h0 = __floats2half2_rn(xv[t].x, xv[t].y);
            __half2 h1 = __floats2half2_rn(xv[t].z, xv[t].w);
            *reinterpret_cast<uint2*>(g_xh + (size_t)(tok0 + t) * D_DIM + d0 + lane * 4) =
                make_uint2(*reinterpret_cast<uint32_t*>(&h0), *reinterpret_cast<uint32_t*>(&h1));
        }
#pragma unroll
        for (int e = 0; e < NE; e++) {
            float4 wv = *reinterpret_cast<const float4*>(rw + e * D_DIM + d0 + lane * 4);
#pragma unroll
            for (int t = 0; t < 4; t++)
                acc[t][e] += xv[t].x * wv.x + xv[t].y * wv.y + xv[t].z * wv.z + xv[t].w * wv.w;
        }
    }

#pragma unroll
    for (int t = 0; t < 4; t++) {
        float la[NE];
#pragma unroll
        for (int e = 0; e < NE; e++) {
            float v = acc[t][e];
#pragma unroll
            for (int off = 16; off > 0; off >>= 1)
                v += __shfl_down_sync(0xffffffffu, v, off);
            la[e] = v;
        }
        if (lane == 0) {
            int tok = tok0 + t;
            float* lo = logits + (size_t)tok * NE;
#pragma unroll
            for (int e = 0; e < NE; e++) lo[e] = la[e];
            float m = la[0];
#pragma unroll
            for (int e = 1; e < NE; e++) m = fmaxf(m, la[e]);
            float p[NE], s = 0.f;
#pragma unroll
            for (int e = 0; e < NE; e++) { p[e] = __expf(la[e] - m); s += p[e]; }
            float inv = 1.f / s;
            int i1 = 0; float v1 = la[0];
#pragma unroll
            for (int e = 1; e < NE; e++) if (la[e] > v1) { v1 = la[e]; i1 = e; }
            int i2 = -1; float v2 = -1e30f;
#pragma unroll
            for (int e = 0; e < NE; e++) if (e != i1 && la[e] > v2) { v2 = la[e]; i2 = e; }
            g_te[2 * tok]     = i1; g_tw[2 * tok]     = p[i1] * inv;
            g_te[2 * tok + 1] = i2; g_tw[2 * tok + 1] = p[i2] * inv;
            atomicAdd(&g_counts[i1], 1);
            atomicAdd(&g_counts[i2], 1);
        }
    }
}

__global__ void k_setup() {
    if (threadIdx.x == 0 && blockIdx.x == 0) {
        int off = 0, t1 = 0, t2 = 0;
        for (int e = 0; e < NE; e++) {
            g_offsets[e] = off; g_cursor[e] = off;
            int c = g_counts[e]; off += c;
            g_tp1[e] = t1; g_tp2[e] = t2;
            int rt = (c + ROWT - 1) >> 7;
            t1 += rt * CT1; t2 += rt * CT2;
        }
        g_offsets[NE] = off; g_tp1[NE] = t1; g_tp2[NE] = t2;
    }
}

// block-aggregated scatter: smem histogram + 16 global atomics per block.
__global__ __launch_bounds__(128) void k_scatter() {
    __shared__ int hist[NE], base[NE];
    int tid = threadIdx.x;
    if (tid < NE) hist[tid] = 0;
    __syncthreads();
    int t = blockIdx.x * 128 + tid;
    int2  ee = *reinterpret_cast<const int2*>(&g_te[2 * t]);
    float2 ww = *reinterpret_cast<const float2*>(&g_tw[2 * t]);
    int r0 = atomicAdd(&hist[ee.x], 1);
    int r1 = atomicAdd(&hist[ee.y], 1);
    __syncthreads();
    if (tid < NE) base[tid] = atomicAdd(&g_cursor[tid], hist[tid]);
    __syncthreads();
    int p0 = base[ee.x] + r0, p1 = base[ee.y] + r1;
    g_idx[p0] = t; g_wgt[p0] = ww.x;
    g_idx[p1] = t; g_wgt[p1] = ww.y;
}

// ---------------- fp32 -> fp16 weight converts ----------------
__global__ __launch_bounds__(256) void k_cvt_gu(const float4* __restrict__ gw,
                                                const float4* __restrict__ uw) {
    size_t i = (size_t)blockIdx.x * 256 + threadIdx.x;
    const size_t N4 = (size_t)NE * D_DIM * F_DIM / 4;
    const float4* src = (i < N4) ? gw : uw;
    __half* dst = (i < N4) ? g_gwh : g_uwh;
    size_t j = (i < N4) ? i : i - N4;
    float4 v = src[j];
    __half2 h0 = __floats2half2_rn(v.x, v.y);
    __half2 h1 = __floats2half2_rn(v.z, v.w);
    reinterpret_cast<uint2*>(dst)[j] =
        make_uint2(*reinterpret_cast<uint32_t*>(&h0), *reinterpret_cast<uint32_t*>(&h1));
}
__global__ __launch_bounds__(256) void k_cvt_d_zero(const float4* __restrict__ dw,
                                                    float4* __restrict__ out4) {
    size_t i = (size_t)blockIdx.x * 256 + threadIdx.x;
    float4 v = dw[i];
    __half2 h0 = __floats2half2_rn(v.x, v.y);
    __half2 h1 = __floats2half2_rn(v.z, v.w);
    reinterpret_cast<uint2*>(g_dwh)[i] =
        make_uint2(*reinterpret_cast<uint32_t*>(&h0), *reinterpret_cast<uint32_t*>(&h1));
    out4[i] = make_float4(0.f, 0.f, 0.f, 0.f);
}

// ---------------- GEMM1: H = silu(X Gw) * (X Uw) ----------------
// CTA 128 rows x 64 cols (gate+up), 256 threads, K-tile 64, 3-stage, 2 CTAs/SM.
__global__ __launch_bounds__(256, 2) void k_mma1() {
    extern __shared__ __align__(16) char smraw[];
    uint32_t sb = smem_u32(smraw);
    __shared__ int info[3];

    int tid = threadIdx.x, w = tid >> 5, l = tid & 31;
    if (tid == 0) {
        int b = blockIdx.x, e = -1;
        if (b < g_tp1[NE]) {
#pragma unroll
            for (int i = 0; i < NE; i++) if (b < g_tp1[i + 1]) { e = i; break; }
        }
        info[0] = e;
        if (e >= 0) { int t = b - g_tp1[e]; info[1] = (t >> 5) << 7; info[2] = (t & 31) << 6; }
    }
    __syncthreads();
    int e = info[0];
    if (e < 0) return;
    int row0 = info[1], col0 = info[2];
    int off = g_offsets[e], n = g_offsets[e + 1] - off;

    const __half* srcA[4]; uint32_t dstA[4];
#pragma unroll
    for (int i = 0; i < 4; i++) {
        int id = tid + i * 256, ar = id >> 3, ch = id & 7;
        int r = row0 + ar; if (r > n - 1) r = n - 1;
        srcA[i] = g_xh + (size_t)g_idx[off + r] * D_DIM + ch * 8;
        dstA[i] = sb + ar * 144 + ch * 16;
    }
    const __half* srcG[2]; const __half* srcU[2]; uint32_t dstB[2];
#pragma unroll
    for (int i = 0; i < 2; i++) {
        int id = tid + i * 256, br = id >> 3, bc = id & 7;
        srcG[i] = g_gwh + ((size_t)e * D_DIM + br) * F_DIM + col0 + bc * 8;
        srcU[i] = g_uwh + ((size_t)e * D_DIM + br) * F_DIM + col0 + bc * 8;
        dstB[i] = sb + ASZ + br * 144 + bc * 16;
    }

    auto load = [&](int kt) {
        uint32_t s = (uint32_t)(kt % 3) * STG1;
        size_t kG = (size_t)kt * 64 * F_DIM;
#pragma unroll
        for (int i = 0; i < 4; i++) cpa16(dstA[i] + s, srcA[i] + kt * 64);
#pragma unroll
        for (int i = 0; i < 2; i++) cpa16(dstB[i] + s, srcG[i] + kG);
#pragma unroll
        for (int i = 0; i < 2; i++) cpa16(dstB[i] + s + 9216, srcU[i] + kG);
        CP_COMMIT();
    };
    load(0); load(1);

    float cg[4][2][4], cu[4][2][4];
#pragma unroll
    for (int mi = 0; mi < 4; mi++)
#pragma unroll
        for (int ni = 0; ni < 2; ni++)
#pragma unroll
            for (int j = 0; j < 4; j++) { cg[mi][ni][j] = 0.f; cu[mi][ni][j] = 0.f; }

    int wm = w >> 2, wn = w & 3;
    int lr = l & 15, lc = l >> 4;
    uint32_t aOff = (uint32_t)((wm * 64 + lr) * 144 + lc * 16);
    uint32_t gOff = (uint32_t)(ASZ + lr * 144 + (wn * 16 + lc * 8) * 2);
    uint32_t uOff = gOff + 9216;

    for (int kt = 0; kt < KT1; kt++) {
        if (kt < KT1 - 1) CP_WAIT(1); else CP_WAIT(0);
        __syncthreads();
        if (kt + 2 < KT1) load(kt + 2);
        uint32_t s = sb + (uint32_t)(kt % 3) * STG1;
#pragma unroll
        for (int ks = 0; ks < 4; ks++) {
            uint32_t a[4][4], bg[4], bu[4];
#pragma unroll
            for (int mi = 0; mi < 4; mi++)
                ldsm4(a[mi], s + aOff + mi * 2304 + ks * 32);
            ldsm4t(bg, s + gOff + ks * 2304);
            ldsm4t(bu, s + uOff + ks * 2304);
#pragma unroll
            for (int mi = 0; mi < 4; mi++)
#pragma unroll
                for (int ni = 0; ni < 2; ni++) {
                    mma16816(cg[mi][ni], a[mi], &bg[2 * ni]);
                    mma16816(cu[mi][ni], a[mi], &bu[2 * ni]);
                }
        }
    }

    // epilogue: silu(g)*u -> smem tile (144B stride) -> coalesced 16B stores
    __syncthreads();
#pragma unroll
    for (int mi = 0; mi < 4; mi++) {
        int rl = wm * 64 + mi * 16 + (l >> 2);
        int rh = rl + 8;
#pragma unroll
        for (int ni = 0; ni < 2; ni++) {
            int cb = (wn * 16 + ni * 8 + 2 * (l & 3)) * 2;
            float g0 = cg[mi][ni][0], g1 = cg[mi][ni][1], g2 = cg[mi][ni][2], g3 = cg[mi][ni][3];
            float h0 = g0 * __fdividef(1.f, 1.f + __expf(-g0)) * cu[mi][ni][0];
            float h1 = g1 * __fdividef(1.f, 1.f + __expf(-g1)) * cu[mi][ni][1];
            float h2 = g2 * __fdividef(1.f, 1.f + __expf(-g2)) * cu[mi][ni][2];
            float h3 = g3 * __fdividef(1.f, 1.f + __expf(-g3)) * cu[mi][ni][3];
            *reinterpret_cast<__half2*>(smraw + rl * 144 + cb) = __floats2half2_rn(h0, h1);
            *reinterpret_cast<__half2*>(smraw + rh * 144 + cb) = __floats2half2_rn(h2, h3);
        }
    }
    __syncthreads();
#pragma unroll
    for (int i = 0; i < 4; i++) {
        int id = tid + i * 256, r = id >> 3, ch = id & 7;
        if (row0 + r < n)
            *reinterpret_cast<uint4*>(&g_H[(size_t)(off + row0 + r) * F_DIM + col0 + ch * 8]) =
                *reinterpret_cast<const uint4*>(smraw + r * 144 + ch * 16);
    }
}

// ---------------- GEMM2: out += w * (H Dw), deterministic red.global ----------------
// CTA 128 rows x 128 cols, 256 threads, K-tile 64, 3-stage, 2 CTAs/SM.
__global__ __launch_bounds__(256, 2) void k_mma2(float* __restrict__ out) {
    extern __shared__ __align__(16) char smraw[];
    uint32_t sb = smem_u32(smraw);
    __shared__ int info[3];

    int tid = threadIdx.x, w = tid >> 5, l = tid & 31;
    if (tid == 0) {
        int b = blockIdx.x, e = -1;
        if (b < g_tp2[NE]) {
#pragma unroll
            for (int i = 0; i < NE; i++) if (b < g_tp2[i + 1]) { e = i; break; }
        }
        info[0] = e;
        if (e >= 0) { int t = b - g_tp2[e]; info[1] = (t >> 3) << 7; info[2] = (t & 7) << 7; }
    }
    __syncthreads();
    int e = info[0];
    if (e < 0) return;
    int row0 = info[1], col0 = info[2];
    int off = g_offsets[e], n = g_offsets[e + 1] - off;

    const __half* srcA[4]; uint32_t dstA[4];
#pragma unroll
    for (int i = 0; i < 4; i++) {
        int id = tid + i * 256, ar = id >> 3, ch = id & 7;
        int r = row0 + ar; if (r > n - 1) r = n - 1;
        srcA[i] = g_H + (size_t)(off + r) * F_DIM + ch * 8;
        dstA[i] = sb + ar * 144 + ch * 16;
    }
    const __half* srcB[4]; uint32_t dstB[4];
#pragma unroll
    for (int i = 0; i < 4; i++) {
        int id = tid + i * 256, brw = id >> 4, ch = id & 15;
        srcB[i] = g_dwh + ((size_t)e * F_DIM + brw) * D_DIM + col0 + ch * 8;
        dstB[i] = sb + ASZ + brw * 272 + ch * 16;
    }

    auto load = [&](int kt) {
        uint32_t s = (uint32_t)(kt % 3) * STG2;
        size_t kB = (size_t)kt * 64 * D_DIM;
#pragma unroll
        for (int i = 0; i < 4; i++) cpa16(dstA[i] + s, srcA[i] + kt * 64);
#pragma unroll
        for (int i = 0; i < 4; i++) cpa16(dstB[i] + s, srcB[i] + kB);
        CP_COMMIT();
    };
    load(0); load(1);

    float cc[4][4][4];
#pragma unroll
    for (int mi = 0; mi < 4; mi++)
#pragma unroll
        for (int ni = 0; ni < 4; ni++)
#pragma unroll
            for (int j = 0; j < 4; j++) cc[mi][ni][j] = 0.f;

    int wm = w >> 2, wn = w & 3;
    int lr = l & 15, lc = l >> 4;
    uint32_t aOff = (uint32_t)((wm * 64 + lr) * 144 + lc * 16);
    uint32_t bOff = (uint32_t)(ASZ + lr * 272 + (wn * 32 + lc * 8) * 2);

    for (int kt = 0; kt < KT2; kt++) {
        if (kt < KT2 - 1) CP_WAIT(1); else CP_WAIT(0);
        __syncthreads();
        if (kt + 2 < KT2) load(kt + 2);
        uint32_t s = sb + (uint32_t)(kt % 3) * STG2;
#pragma unroll
        for (int ks = 0; ks < 4; ks++) {
            uint32_t a[4][4], bf[2][4];
#pragma unroll
            for (int mi = 0; mi < 4; mi++)
                ldsm4(a[mi], s + aOff + mi * 2304 + ks * 32);
#pragma unroll
            for (int nf = 0; nf < 2; nf++)
                ldsm4t(bf[nf], s + bOff + ks * 4352 + nf * 32);
#pragma unroll
            for (int mi = 0; mi < 4; mi++)
#pragma unroll
                for (int ni = 0; ni < 4; ni++)
                    mma16816(cc[mi][ni], a[mi], &bf[ni >> 1][2 * (ni & 1)]);
        }
    }

    // epilogue: deterministic fp32 reduction straight into out (exactly 2 adds/element).
    int cbase = col0 + wn * 32 + 2 * (l & 3);
#pragma unroll
    for (int mi = 0; mi < 4; mi++) {
        int rl = row0 + wm * 64 + mi * 16 + (l >> 2);
        int rh = rl + 8;
        if (rl < n) {
            float wl = g_wgt[off + rl];
            float* po = out + (size_t)g_idx[off + rl] * D_DIM + cbase;
#pragma unroll
            for (int ni = 0; ni < 4; ni++)
                redv2(po + ni * 8, wl * cc[mi][ni][0], wl * cc[mi][ni][1]);
        }
        if (rh < n) {
            float wh = g_wgt[off + rh];
            float* po = out + (size_t)g_idx[off + rh] * D_DIM + cbase;
#pragma unroll
            for (int ni = 0; ni < 4; ni++)
                redv2(po + ni * 8, wh * cc[mi][ni][2], wh * cc[mi][ni][3]);
        }
    }
}

// ---------------- launch ----------------
extern "C" void kernel_launch(void* const* d_in, const int* in_sizes, int n_in,
                              void* d_out, int out_size) {
    const float* x  = (const float*)d_in[0];
    const float* rw = (const float*)d_in[1];
    const float* gw = (const float*)d_in[2];
    const float* uw = (const float*)d_in[3];
    const float* dw = (const float*)d_in[4];
    float* out    = (float*)d_out;
    float* logits = out + (size_t)T_TOK * D_DIM;

    static cudaStream_t s1 = nullptr;
    static cudaEvent_t evF = nullptr, ev1 = nullptr, ev2 = nullptr;
    static void* counts_ptr = nullptr;
    static int init_done = 0;
    if (!init_done) {
        cudaFuncSetAttribute(k_mma1, cudaFuncAttributeMaxDynamicSharedMemorySize, SMEM1);
        cudaFuncSetAttribute(k_mma2, cudaFuncAttributeMaxDynamicSharedMemorySize, SMEM2);
        cudaStreamCreateWithFlags(&s1, cudaStreamNonBlocking);
        cudaEventCreateWithFlags(&evF, cudaEventDisableTiming);
        cudaEventCreateWithFlags(&ev1, cudaEventDisableTiming);
        cudaEventCreateWithFlags(&ev2, cudaEventDisableTiming);
        cudaGetSymbolAddress(&counts_ptr, g_counts);
        init_done = 1;
    }

    // zero the expert counters (replaces k_init launch)
    cudaMemsetAsync(counts_ptr, 0, NE * sizeof(int), 0);

    // single side stream, CHAINED: gu first (gates GEMM1, full spare BW),
    // then dw+zero (only needed by GEMM2, overlaps GEMM1).
    cudaEventRecord(evF, 0);
    cudaStreamWaitEvent(s1, evF, 0);
    k_cvt_gu<<<65536, 256, 0, s1>>>((const float4*)gw, (const float4*)uw);
    cudaEventRecord(ev1, s1);
    k_cvt_d_zero<<<32768, 256, 0, s1>>>((const float4*)dw, (float4*)out);
    cudaEventRecord(ev2, s1);

    k_router<<<T_TOK / 32, 256>>>(x, rw, logits);
    k_setup<<<1, 1>>>();
    k_scatter<<<T_TOK / 128, 128>>>();

    cudaStreamWaitEvent(0, ev1, 0);
    k_mma1<<<MAXT1, 256, SMEM1>>>();
    cudaStreamWaitEvent(0, ev2, 0);
    k_mma2<<<MAXT2, 256, SMEM2>>>(out);
}